// round 14
// baseline (speedup 1.0000x reference)
#include <cuda_runtime.h>
#include <math.h>

#define DINLINE __device__ __forceinline__

// ---------------- problem constants ----------------
constexpr int kB  = 8;
constexpr int kF  = 257;
constexpr int kL  = 497;
constexpr int kFL = kF * kL;            // 127729
constexpr int kLN = 62;
constexpr int kT  = kL - kLN;           // 435
constexpr int kF2 = 129;
constexpr int kL2 = 249;
constexpr int kFL2 = kF2 * kL2;         // 32121
constexpr int kNBF = kB * kF;           // 2056
constexpr float kBETA = 0.995f;

// d_out layout (VERIFIED): float32, complex outputs stored as REAL PART ONLY.
constexpr long long OFF_WTC  = 0;
constexpr long long OFF_XHAT = 16349312;
constexpr long long OFF_Y    = 17371144;
constexpr long long OFF_WC   = 33720456;
constexpr long long OFF_WS2  = 41895112;
constexpr long long OFF_GATE = 42916944;
constexpr long long OUT_TOTAL = 75615568;

// ---------------- device scratch ----------------
__device__ float  g_rtf [(size_t)kB * 16 * kFL];
__device__ float  g_e1  [(size_t)kB * 32 * kFL];
__device__ float  g_skip[(size_t)kB * 32 * kFL];
__device__ float  g_d1  [(size_t)kB * 64 * kFL2];
__device__ float  g_mid [(size_t)kB * 64 * kFL2];
__device__ float  g_u2  [(size_t)kB * 32 * kFL];
__device__ float2 g_IS  [kNBF * 64];
__device__ float2 g_RS  [kNBF * 64];

// ---- packed fp32x2 helpers (FFMA2) ----
DINLINE unsigned long long pack2(float a, float b) {
    unsigned long long r;
    asm("mov.b64 %0, {%1, %2};" : "=l"(r) : "f"(a), "f"(b));
    return r;
}
DINLINE float2 unpack2(unsigned long long v) {
    float2 r;
    asm("mov.b64 {%0, %1}, %2;" : "=f"(r.x), "=f"(r.y) : "l"(v));
    return r;
}
DINLINE void ffma2(unsigned long long& acc, unsigned long long x, unsigned long long w) {
    asm("fma.rn.f32x2 %0, %1, %2, %0;" : "+l"(acc) : "l"(x), "l"(w));
}

// =====================================================================
// Kernel 1: Rn + Newton-Schulz -> g_IS (Rn^-1/2), g_RS (Rn^+1/2)
// =====================================================================
struct PrepSh {
    float2 stage[8 * 62];
    float2 buf[4][64];
};

DINLINE void mm8(float2* C, const float2* A, const float2* B, int lane) {
    #pragma unroll
    for (int r = 0; r < 2; ++r) {
        int e  = lane + 32 * r;
        int mm = e >> 3, nn = e & 7;
        float2 acc = make_float2(0.f, 0.f);
        #pragma unroll
        for (int k = 0; k < 8; ++k) {
            float2 a  = A[mm * 8 + k];
            float2 bv = B[k * 8 + nn];
            acc.x += a.x * bv.x - a.y * bv.y;
            acc.y += a.x * bv.y + a.y * bv.x;
        }
        C[e] = acc;
    }
}

__global__ __launch_bounds__(256) void k_prep(const float* __restrict__ Y) {
    __shared__ PrepSh sh[8];
    const int lane = threadIdx.x & 31;
    const int wrp  = threadIdx.x >> 5;
    const int bf   = blockIdx.x * 8 + wrp;
    if (bf >= kNBF) return;
    PrepSh& S = sh[wrp];
    const int b = bf / kF;
    const int f = bf - b * kF;

    for (int i = lane; i < 8 * 62; i += 32) {
        int m = i / 62, t = i - m * 62;
        size_t base = (size_t)f * kL + t;
        S.stage[i] = make_float2(Y[((size_t)(b * 16 + m)) * kFL + base],
                                 Y[((size_t)(b * 16 + 8 + m)) * kFL + base]);
    }
    __syncwarp();

    for (int e = lane; e < 64; e += 32) {
        int mm = e >> 3, nn = e & 7;
        float2 acc = make_float2(0.f, 0.f);
        for (int t = 0; t < 62; ++t) {
            float2 a = S.stage[mm * 62 + t];
            float2 c = S.stage[nn * 62 + t];
            acc.x += a.x * c.x + a.y * c.y;
            acc.y += a.y * c.x - a.x * c.y;
        }
        acc.x *= (1.f / 62.f);
        acc.y *= (1.f / 62.f);
        if (mm == nn) acc.x += 1e-4f;
        S.buf[0][e] = acc;
    }
    __syncwarp();

    float tr = 0.f;
    #pragma unroll
    for (int k = 0; k < 8; ++k) tr += S.buf[0][k * 9].x;
    const float invtr = 1.f / tr;

    for (int e = lane; e < 64; e += 32) {
        float2 v = S.buf[0][e];
        S.buf[0][e] = make_float2(v.x * invtr, v.y * invtr);
        S.buf[1][e] = make_float2(((e >> 3) == (e & 7)) ? 1.f : 0.f, 0.f);
    }
    __syncwarp();

    int iY = 0, iZ = 1, iT = 2, iS = 3;
    for (int it = 0; it < 18; ++it) {
        mm8(S.buf[iT], S.buf[iZ], S.buf[iY], lane);
        __syncwarp();
        for (int e = lane; e < 64; e += 32) {
            float2 pv = S.buf[iT][e];
            S.buf[iT][e] = make_float2((((e >> 3) == (e & 7)) ? 1.5f : 0.f) - 0.5f * pv.x,
                                       -0.5f * pv.y);
        }
        __syncwarp();
        mm8(S.buf[iS], S.buf[iY], S.buf[iT], lane);
        __syncwarp();
        mm8(S.buf[iY], S.buf[iT], S.buf[iZ], lane);
        __syncwarp();
        int tmp = iY; iY = iS; iS = iZ; iZ = tmp;
    }

    const float sq = sqrtf(tr), isq = 1.f / sq;
    for (int e = lane; e < 64; e += 32) {
        float2 y = S.buf[iY][e];
        float2 z = S.buf[iZ][e];
        g_RS[bf * 64 + e] = make_float2(y.x * sq,  y.y * sq);
        g_IS[bf * 64 + e] = make_float2(z.x * isq, z.y * isq);
    }
}

// =====================================================================
// Kernel 2: whitening + PAST-d scan + RTF -> g_rtf
// =====================================================================
DINLINE float2 shfl2(float2 v, int src) {
    float2 r;
    r.x = __shfl_sync(0xffffffffu, v.x, src, 8);
    r.y = __shfl_sync(0xffffffffu, v.y, src, 8);
    return r;
}

__global__ __launch_bounds__(256) void k_scan(const float* __restrict__ Y) {
    const int lane = threadIdx.x & 31;
    const int seg  = lane >> 3;
    const int m    = lane & 7;
    const int g    = (blockIdx.x * 8 + (threadIdx.x >> 5)) * 4 + seg;
    const bool valid = (g < kNBF);
    const int gc = valid ? g : 0;
    const int b = gc / kF;
    const int f = gc - b * kF;

    float2 ISr[8], RSr[8];
    #pragma unroll
    for (int n = 0; n < 8; ++n) {
        ISr[n] = g_IS[gc * 64 + m * 8 + n];
        RSr[n] = g_RS[gc * 64 + m * 8 + n];
    }

    const float* Yre = Y + ((size_t)(b * 16 + m)) * kFL + (size_t)f * kL;
    const float* Yim = Yre + (size_t)8 * kFL;
    float* Rre = g_rtf + ((size_t)(b * 16 + m)) * kFL + (size_t)f * kL;
    float* Rim = Rre + (size_t)8 * kFL;

    if (valid) {
        for (int t = 0; t < kLN; ++t) { Rre[t] = 0.f; Rim[t] = 0.f; }
    }

    float2 w = make_float2(0.f, 0.f);
    float  d = 1.f;

    for (int t = 0; t < kT; ++t) {
        float2 yc = make_float2(Yre[kLN + t], Yim[kLN + t]);
        float2 y = make_float2(0.f, 0.f);
        #pragma unroll
        for (int n = 0; n < 8; ++n) {
            float2 v = shfl2(yc, n);
            y.x += ISr[n].x * v.x - ISr[n].y * v.y;
            y.y += ISr[n].x * v.y + ISr[n].y * v.x;
        }
        if (t == 0) {
            float nn = y.x * y.x + y.y * y.y;
            #pragma unroll
            for (int o = 4; o; o >>= 1) nn += __shfl_xor_sync(0xffffffffu, nn, o, 8);
            float inv = 1.f / (sqrtf(nn) + 1e-8f);
            w = make_float2(y.x * inv, y.y * inv);
            d = 1.f;
        }
        float2 p = make_float2(y.x * w.x + y.y * w.y, y.y * w.x - y.x * w.y);
        #pragma unroll
        for (int o = 4; o; o >>= 1) {
            p.x += __shfl_xor_sync(0xffffffffu, p.x, o, 8);
            p.y += __shfl_xor_sync(0xffffffffu, p.y, o, 8);
        }
        d = kBETA * d + (p.x * p.x + p.y * p.y);
        float2 e = make_float2(y.x - (w.x * p.x - w.y * p.y),
                               y.y - (w.x * p.y + w.y * p.x));
        float id = 1.f / d;
        float2 cpd = make_float2(p.x * id, -p.y * id);
        w.x += e.x * cpd.x - e.y * cpd.y;
        w.y += e.x * cpd.y + e.y * cpd.x;

        float2 a = make_float2(0.f, 0.f);
        #pragma unroll
        for (int n = 0; n < 8; ++n) {
            float2 v = shfl2(w, n);
            a.x += RSr[n].x * v.x - RSr[n].y * v.y;
            a.y += RSr[n].x * v.y + RSr[n].y * v.x;
        }
        float2 rf = shfl2(a, 3);
        rf.x += 1e-6f;
        float inv2 = 1.f / (rf.x * rf.x + rf.y * rf.y);
        float ox = (a.x * rf.x + a.y * rf.y) * inv2;
        float oy = (a.y * rf.x - a.x * rf.y) * inv2;
        if (valid) { Rre[kLN + t] = ox; Rim[kLN + t] = oy; }
    }
}

// =====================================================================
// Kernel 3: Y echo + W_stage2 zeros (float4)
// =====================================================================
__global__ void k_copy(const float* __restrict__ Y, float* __restrict__ out) {
    const int NY4 = 16349312 / 4;
    const int NZ4 = 1021832 / 4;
    int i = blockIdx.x * blockDim.x + threadIdx.x;
    if (i < NY4) {
        reinterpret_cast<float4*>(out + OFF_Y)[i] = reinterpret_cast<const float4*>(Y)[i];
    } else if (i < NY4 + NZ4) {
        reinterpret_cast<float4*>(out + OFF_WS2)[i - NY4] = make_float4(0.f, 0.f, 0.f, 0.f);
    }
}

// =====================================================================
// Direct conv 3x3 (SAME): P=2 strided pixels/thread, FFMA2 accumulators,
// input double-buffer prefetch + ROLLING WEIGHT PREFETCH.
// MODE_IN : 1=concat(Y,g_rtf) 2=upsample(g_mid) 3=concat(g_u2,g_skip) 4=g_e1 5=g_d1
// MODE_OUT: 1=enc1(relu->g_e1 + fused gate) 2=out layer 10=g_d1 11=g_mid 12=g_u2
// =====================================================================
template<int CIN, int COUT, int STRIDE, int MODE_IN, int MODE_OUT, int P>
__global__ __launch_bounds__(256, 2) void k_conv(
    const float* __restrict__ Yin,
    const float* __restrict__ wgt,
    const float* __restrict__ bias,
    const float* __restrict__ gw,
    const float* __restrict__ gb,
    float* __restrict__ dout,
    int H_IN, int W_IN, int H_OUT, int W_OUT, int nTiles)
{
    __shared__ __align__(16) float wsh[CIN * 9 * COUT];
    __shared__ float bsh[COUT];
    __shared__ __align__(16) float gsh[(MODE_OUT == 1) ? 1024 : 4];
    __shared__ float gbsh[(MODE_OUT == 1) ? 32 : 1];

    const int b     = blockIdx.z / nTiles;
    const int ct    = blockIdx.z - b * nTiles;
    const int cbase = ct * COUT;

    for (int i = threadIdx.x; i < CIN * 9 * COUT; i += 256) {
        int ci = i / (9 * COUT);
        int r  = i - ci * 9 * COUT;
        int t  = r / COUT;
        int co = r - t * COUT;
        wsh[i] = wgt[((cbase + co) * CIN + ci) * 9 + t];
    }
    for (int i = threadIdx.x; i < COUT; i += 256) bsh[i] = bias[cbase + i];
    if (MODE_OUT == 1) {
        for (int i = threadIdx.x; i < 1024; i += 256) {
            int ci = i >> 5, co = i & 31;
            gsh[ci * 32 + co] = gw[co * 32 + ci];
        }
        if (threadIdx.x < 32) gbsh[threadIdx.x] = gb[threadIdx.x];
    }
    __syncthreads();

    const int lane = threadIdx.x & 31;
    const int f    = blockIdx.y * 8 + (threadIdx.x >> 5);
    if (f >= H_OUT) return;
    const int Lb   = blockIdx.x * (32 * P) + lane;

    int rowbase[3];
    #pragma unroll
    for (int kh = 0; kh < 3; ++kh) {
        if (MODE_IN == 2) {
            int r = f + kh - 1;
            rowbase[kh] = (r >= 0 && r < 257) ? (((2 * r + 1) * 129) / 514) * kL2 : -1;
        } else {
            int r = f * STRIDE + kh - 1;
            rowbase[kh] = (r >= 0 && r < H_IN) ? r * W_IN : -1;
        }
    }
    int ccol[P][3];
    #pragma unroll
    for (int p = 0; p < P; ++p) {
        #pragma unroll
        for (int kw = 0; kw < 3; ++kw) {
            if (MODE_IN == 2) {
                int c = Lb + 32 * p + kw - 1;
                ccol[p][kw] = (c >= 0 && c < 497) ? ((2 * c + 1) * 249) / 994 : -1;
            } else {
                int c = (Lb + 32 * p) * STRIDE + kw - 1;
                ccol[p][kw] = (c >= 0 && c < W_IN) ? c : -1;
            }
        }
    }

    auto srcPtr = [&](int ci) -> const float* {
        if (MODE_IN == 1)
            return (ci < 16) ? Yin + ((size_t)(b * 16 + ci)) * kFL
                             : g_rtf + ((size_t)(b * 16 + ci - 16)) * kFL;
        else if (MODE_IN == 4)
            return g_e1 + ((size_t)(b * 32 + ci)) * kFL;
        else if (MODE_IN == 5)
            return g_d1 + ((size_t)(b * 64 + ci)) * kFL2;
        else if (MODE_IN == 2)
            return g_mid + ((size_t)(b * 64 + ci)) * kFL2;
        else
            return (ci < 32) ? g_u2 + ((size_t)(b * 32 + ci)) * kFL
                             : g_skip + ((size_t)(b * 32 + ci - 32)) * kFL;
    };
    auto loadIn = [&](int ci, float* xv) {
        const float* src = srcPtr(ci);
        #pragma unroll
        for (int t = 0; t < 9; ++t) {
            const int kh = t / 3, kw = t - kh * 3;
            #pragma unroll
            for (int p = 0; p < P; ++p)
                xv[t * P + p] = (rowbase[kh] >= 0 && ccol[p][kw] >= 0)
                                  ? __ldg(src + rowbase[kh] + ccol[p][kw]) : 0.0f;
        }
    };

    constexpr int C2 = COUT / 2;
    constexpr int NW = 9 * (COUT / 4);          // # ulonglong2 weight vectors per c_in
    unsigned long long acc2[P * C2];
    #pragma unroll
    for (int i = 0; i < C2; ++i) {
        unsigned long long bv = pack2(bsh[2 * i], bsh[2 * i + 1]);
        #pragma unroll
        for (int p = 0; p < P; ++p) acc2[p * C2 + i] = bv;
    }

    float xv[9 * P], xvn[9 * P];
    loadIn(0, xv);

    #pragma unroll 1
    for (int ci = 0; ci < CIN; ++ci) {
        if (ci + 1 < CIN) loadIn(ci + 1, xvn);   // prefetch next c_in's inputs

        const ulonglong2* wrow = reinterpret_cast<const ulonglong2*>(wsh + ci * 9 * COUT);
        ulonglong2 wv = wrow[0];                  // rolling weight register
        unsigned long long xx[P];
        #pragma unroll
        for (int idx = 0; idx < NW; ++idx) {
            const int t = idx / (COUT / 4);
            const int q = idx - t * (COUT / 4);
            if (q == 0) {
                #pragma unroll
                for (int p = 0; p < P; ++p) xx[p] = pack2(xv[t * P + p], xv[t * P + p]);
            }
            ulonglong2 wnx = wrow[(idx + 1 < NW) ? idx + 1 : idx];   // prefetch next LDS
            #pragma unroll
            for (int p = 0; p < P; ++p) {
                ffma2(acc2[p * C2 + 2 * q + 0], xx[p], wv.x);
                ffma2(acc2[p * C2 + 2 * q + 1], xx[p], wv.y);
            }
            wv = wnx;
        }
        #pragma unroll
        for (int i = 0; i < 9 * P; ++i) xv[i] = xvn[i];
    }

    // ---------------- epilogues ----------------
    if (MODE_OUT == 1) {
        // compute both pixels' e1 first, then gate with ci-outer loop (shared LDS)
        float e1v[P][32];
        #pragma unroll
        for (int p = 0; p < P; ++p) {
            #pragma unroll
            for (int i = 0; i < C2; ++i) {
                float2 v = unpack2(acc2[p * C2 + i]);
                e1v[p][2 * i]     = fmaxf(v.x, 0.0f);
                e1v[p][2 * i + 1] = fmaxf(v.y, 0.0f);
            }
        }
        #pragma unroll
        for (int p = 0; p < P; ++p) {
            const int lp = Lb + 32 * p;
            if (lp >= W_OUT) continue;
            const int pix = f * W_OUT + lp;
            float* e1dst = g_e1 + ((size_t)b * 32) * kFL + pix;
            #pragma unroll
            for (int co = 0; co < 32; ++co) e1dst[(size_t)co * kFL] = e1v[p][co];
        }

        unsigned long long ga2[P][16];
        #pragma unroll
        for (int i = 0; i < 16; ++i) {
            unsigned long long bv = pack2(gbsh[2 * i], gbsh[2 * i + 1]);
            #pragma unroll
            for (int p = 0; p < P; ++p) ga2[p][i] = bv;
        }
        #pragma unroll 1
        for (int ci = 0; ci < 32; ++ci) {
            const ulonglong2* gr = reinterpret_cast<const ulonglong2*>(gsh + ci * 32);
            ulonglong2 gv = gr[0];
            unsigned long long xx[P];
            #pragma unroll
            for (int p = 0; p < P; ++p) xx[p] = pack2(e1v[p][ci], e1v[p][ci]);
            #pragma unroll
            for (int q = 0; q < 8; ++q) {
                ulonglong2 gnx = gr[(q + 1 < 8) ? q + 1 : q];
                #pragma unroll
                for (int p = 0; p < P; ++p) {
                    ffma2(ga2[p][2 * q + 0], xx[p], gv.x);
                    ffma2(ga2[p][2 * q + 1], xx[p], gv.y);
                }
                gv = gnx;
            }
        }
        #pragma unroll
        for (int p = 0; p < P; ++p) {
            const int lp = Lb + 32 * p;
            if (lp >= W_OUT) continue;
            const int pix = f * W_OUT + lp;
            float* gdst = dout + OFF_GATE + ((size_t)b * 32) * kFL + pix;
            float* sdst = g_skip + ((size_t)b * 32) * kFL + pix;
            #pragma unroll
            for (int i = 0; i < 16; ++i) {
                float2 v = unpack2(ga2[p][i]);
                float g0 = 1.0f / (1.0f + __expf(-v.x));
                float g1 = 1.0f / (1.0f + __expf(-v.y));
                gdst[(size_t)(2 * i + 0) * kFL] = g0;
                gdst[(size_t)(2 * i + 1) * kFL] = g1;
                sdst[(size_t)(2 * i + 0) * kFL] = e1v[p][2 * i + 0] * g0;
                sdst[(size_t)(2 * i + 1) * kFL] = e1v[p][2 * i + 1] * g1;
            }
        }
    } else {
        #pragma unroll
        for (int p = 0; p < P; ++p) {
            const int lp = Lb + 32 * p;
            if (lp >= W_OUT) continue;
            const int pix = f * W_OUT + lp;

            float accf[COUT];
            #pragma unroll
            for (int i = 0; i < C2; ++i) {
                float2 v = unpack2(acc2[p * C2 + i]);
                accf[2 * i] = v.x; accf[2 * i + 1] = v.y;
            }

            if (MODE_OUT == 2) {
                float wr[8], wi[8];
                #pragma unroll
                for (int co = 0; co < 16; ++co) {
                    float s = 1.0f / (1.0f + __expf(-accf[co]));
                    dout[OFF_WTC + ((size_t)(b * 16 + co)) * kFL + pix] = s;
                    if (co < 8) wr[co] = s; else wi[co - 8] = s;
                }
                float xr = 0.f;
                const float* ybase = Yin + ((size_t)b * 16) * kFL + pix;
                float* wcdst = dout + OFF_WC + ((size_t)b * 8) * kFL + pix;
                #pragma unroll
                for (int m = 0; m < 8; ++m) {
                    float yr = ybase[(size_t)m * kFL];
                    float yi = ybase[(size_t)(8 + m) * kFL];
                    xr += wr[m] * yr + wi[m] * yi;
                    wcdst[(size_t)m * kFL] = wr[m];
                }
                dout[OFF_XHAT + (size_t)b * kFL + pix] = xr;
            } else {
                float* dst;
                size_t cs;
                if (MODE_OUT == 10)      { dst = g_d1  + ((size_t)(b * 64 + cbase)) * kFL2 + pix; cs = kFL2; }
                else if (MODE_OUT == 11) { dst = g_mid + ((size_t)(b * 64 + cbase)) * kFL2 + pix; cs = kFL2; }
                else                     { dst = g_u2  + ((size_t)(b * 32 + cbase)) * kFL  + pix; cs = kFL;  }
                #pragma unroll
                for (int co = 0; co < COUT; ++co)
                    dst[(size_t)co * cs] = fmaxf(accf[co], 0.0f);
            }
        }
    }
}

// =====================================================================
extern "C" void kernel_launch(void* const* d_in, const int* in_sizes, int n_in,
                              void* d_out, int out_size)
{
    const float *Y = nullptr, *mid_w = nullptr, *gate_w = nullptr, *out_b16 = nullptr;
    const float *w9216[2]  = {nullptr, nullptr};  int n9216  = 0;
    const float *w18432[2] = {nullptr, nullptr};  int n18432 = 0;
    const float *b64[2]    = {nullptr, nullptr};  int nb64   = 0;
    const float *b32[3]    = {nullptr, nullptr, nullptr}; int nb32 = 0;
    for (int i = 0; i < n_in; ++i) {
        const float* p = (const float*)d_in[i];
        switch (in_sizes[i]) {
            case 16349312: if (!Y) Y = p; break;
            case 36864:    mid_w = p; break;
            case 1024:     gate_w = p; break;
            case 16:       out_b16 = p; break;
            case 9216:     if (n9216  < 2) w9216[n9216++]   = p; break;
            case 18432:    if (n18432 < 2) w18432[n18432++] = p; break;
            case 64:       if (nb64   < 2) b64[nb64++]      = p; break;
            case 32:       if (nb32   < 3) b32[nb32++]      = p; break;
            default: break;
        }
    }
    if (!Y || n9216 < 2 || n18432 < 2 || !mid_w || !gate_w ||
        nb64 < 2 || nb32 < 3 || !out_b16)
        return;
    if ((long long)out_size != OUT_TOTAL) return;

    const float* enc1_w = w9216[0];
    const float* out_w  = w9216[1];
    const float* down_w = w18432[0];
    const float* up_w   = w18432[1];
    const float* down_b = b64[0];
    const float* mid_b  = b64[1];
    const float* enc1_b = b32[0];
    const float* gate_b = b32[1];
    const float* up_b   = b32[2];
    float* out = (float*)d_out;

    k_prep<<<257, 256>>>(Y);
    k_scan<<<65, 256>>>(Y);
    k_copy<<<16965, 256>>>(Y, out);

    // enc1: CIN=32, COUT=32, P=2, fused gate
    k_conv<32, 32, 1, 1, 1, 2><<<dim3(8, 33, 8), 256>>>(
        Y, enc1_w, enc1_b, gate_w, gate_b, out, 257, 497, 257, 497, 1);
    // down: CIN=32, COUT=64 in 2 tiles of 32, stride 2
    k_conv<32, 32, 2, 4, 10, 2><<<dim3(4, 17, 16), 256>>>(
        Y, down_w, down_b, nullptr, nullptr, out, 257, 497, 129, 249, 2);
    // mid: CIN=64, COUT=64 in 2 tiles of 32
    k_conv<64, 32, 1, 5, 11, 2><<<dim3(4, 17, 16), 256>>>(
        Y, mid_w, mid_b, nullptr, nullptr, out, 129, 249, 129, 249, 2);
    // up: CIN=64, COUT=32 (upsample gather)
    k_conv<64, 32, 1, 2, 12, 2><<<dim3(8, 33, 8), 256>>>(
        Y, up_w, up_b, nullptr, nullptr, out, 257, 497, 257, 497, 1);
    // out: CIN=64, COUT=16, fused sigmoid/Wc/X_hat
    k_conv<64, 16, 1, 3, 2, 2><<<dim3(8, 33, 8), 256>>>(
        Y, out_w, out_b16, nullptr, nullptr, out, 257, 497, 257, 497, 1);
}

// round 15
// speedup vs baseline: 1.1750x; 1.1750x over previous
#include <cuda_runtime.h>
#include <math.h>

#define DINLINE __device__ __forceinline__

// ---------------- problem constants ----------------
constexpr int kB  = 8;
constexpr int kF  = 257;
constexpr int kL  = 497;
constexpr int kFL = kF * kL;            // 127729
constexpr int kLN = 62;
constexpr int kT  = kL - kLN;           // 435
constexpr int kF2 = 129;
constexpr int kL2 = 249;
constexpr int kFL2 = kF2 * kL2;         // 32121
constexpr int kNBF = kB * kF;           // 2056
constexpr float kBETA = 0.995f;

// d_out layout (VERIFIED): float32, complex outputs stored as REAL PART ONLY.
constexpr long long OFF_WTC  = 0;
constexpr long long OFF_XHAT = 16349312;
constexpr long long OFF_Y    = 17371144;
constexpr long long OFF_WC   = 33720456;
constexpr long long OFF_WS2  = 41895112;
constexpr long long OFF_GATE = 42916944;
constexpr long long OUT_TOTAL = 75615568;

// ---------------- device scratch ----------------
__device__ float  g_rtf [(size_t)kB * 16 * kFL];
__device__ float  g_e1  [(size_t)kB * 32 * kFL];
__device__ float  g_skip[(size_t)kB * 32 * kFL];
__device__ float  g_d1  [(size_t)kB * 64 * kFL2];
__device__ float  g_mid [(size_t)kB * 64 * kFL2];
__device__ float  g_u2  [(size_t)kB * 32 * kFL];
__device__ float2 g_IS  [kNBF * 64];
__device__ float2 g_RS  [kNBF * 64];

// ---- packed fp32x2 helpers (FFMA2) ----
DINLINE unsigned long long pack2(float a, float b) {
    unsigned long long r;
    asm("mov.b64 %0, {%1, %2};" : "=l"(r) : "f"(a), "f"(b));
    return r;
}
DINLINE float2 unpack2(unsigned long long v) {
    float2 r;
    asm("mov.b64 {%0, %1}, %2;" : "=f"(r.x), "=f"(r.y) : "l"(v));
    return r;
}
DINLINE void ffma2(unsigned long long& acc, unsigned long long x, unsigned long long w) {
    asm("fma.rn.f32x2 %0, %1, %2, %0;" : "+l"(acc) : "l"(x), "l"(w));
}

// =====================================================================
// Kernel 1: Rn + Newton-Schulz -> g_IS (Rn^-1/2), g_RS (Rn^+1/2)
// =====================================================================
struct PrepSh {
    float2 stage[8 * 62];
    float2 buf[4][64];
};

DINLINE void mm8(float2* C, const float2* A, const float2* B, int lane) {
    #pragma unroll
    for (int r = 0; r < 2; ++r) {
        int e  = lane + 32 * r;
        int mm = e >> 3, nn = e & 7;
        float2 acc = make_float2(0.f, 0.f);
        #pragma unroll
        for (int k = 0; k < 8; ++k) {
            float2 a  = A[mm * 8 + k];
            float2 bv = B[k * 8 + nn];
            acc.x += a.x * bv.x - a.y * bv.y;
            acc.y += a.x * bv.y + a.y * bv.x;
        }
        C[e] = acc;
    }
}

__global__ __launch_bounds__(256) void k_prep(const float* __restrict__ Y) {
    __shared__ PrepSh sh[8];
    const int lane = threadIdx.x & 31;
    const int wrp  = threadIdx.x >> 5;
    const int bf   = blockIdx.x * 8 + wrp;
    if (bf >= kNBF) return;
    PrepSh& S = sh[wrp];
    const int b = bf / kF;
    const int f = bf - b * kF;

    for (int i = lane; i < 8 * 62; i += 32) {
        int m = i / 62, t = i - m * 62;
        size_t base = (size_t)f * kL + t;
        S.stage[i] = make_float2(Y[((size_t)(b * 16 + m)) * kFL + base],
                                 Y[((size_t)(b * 16 + 8 + m)) * kFL + base]);
    }
    __syncwarp();

    for (int e = lane; e < 64; e += 32) {
        int mm = e >> 3, nn = e & 7;
        float2 acc = make_float2(0.f, 0.f);
        for (int t = 0; t < 62; ++t) {
            float2 a = S.stage[mm * 62 + t];
            float2 c = S.stage[nn * 62 + t];
            acc.x += a.x * c.x + a.y * c.y;
            acc.y += a.y * c.x - a.x * c.y;
        }
        acc.x *= (1.f / 62.f);
        acc.y *= (1.f / 62.f);
        if (mm == nn) acc.x += 1e-4f;
        S.buf[0][e] = acc;
    }
    __syncwarp();

    float tr = 0.f;
    #pragma unroll
    for (int k = 0; k < 8; ++k) tr += S.buf[0][k * 9].x;
    const float invtr = 1.f / tr;

    for (int e = lane; e < 64; e += 32) {
        float2 v = S.buf[0][e];
        S.buf[0][e] = make_float2(v.x * invtr, v.y * invtr);
        S.buf[1][e] = make_float2(((e >> 3) == (e & 7)) ? 1.f : 0.f, 0.f);
    }
    __syncwarp();

    int iY = 0, iZ = 1, iT = 2, iS = 3;
    for (int it = 0; it < 18; ++it) {
        mm8(S.buf[iT], S.buf[iZ], S.buf[iY], lane);
        __syncwarp();
        for (int e = lane; e < 64; e += 32) {
            float2 pv = S.buf[iT][e];
            S.buf[iT][e] = make_float2((((e >> 3) == (e & 7)) ? 1.5f : 0.f) - 0.5f * pv.x,
                                       -0.5f * pv.y);
        }
        __syncwarp();
        mm8(S.buf[iS], S.buf[iY], S.buf[iT], lane);
        __syncwarp();
        mm8(S.buf[iY], S.buf[iT], S.buf[iZ], lane);
        __syncwarp();
        int tmp = iY; iY = iS; iS = iZ; iZ = tmp;
    }

    const float sq = sqrtf(tr), isq = 1.f / sq;
    for (int e = lane; e < 64; e += 32) {
        float2 y = S.buf[iY][e];
        float2 z = S.buf[iZ][e];
        g_RS[bf * 64 + e] = make_float2(y.x * sq,  y.y * sq);
        g_IS[bf * 64 + e] = make_float2(z.x * isq, z.y * isq);
    }
}

// =====================================================================
// Kernel 2: whitening + PAST-d scan + RTF -> g_rtf
// =====================================================================
DINLINE float2 shfl2(float2 v, int src) {
    float2 r;
    r.x = __shfl_sync(0xffffffffu, v.x, src, 8);
    r.y = __shfl_sync(0xffffffffu, v.y, src, 8);
    return r;
}

__global__ __launch_bounds__(256) void k_scan(const float* __restrict__ Y) {
    const int lane = threadIdx.x & 31;
    const int seg  = lane >> 3;
    const int m    = lane & 7;
    const int g    = (blockIdx.x * 8 + (threadIdx.x >> 5)) * 4 + seg;
    const bool valid = (g < kNBF);
    const int gc = valid ? g : 0;
    const int b = gc / kF;
    const int f = gc - b * kF;

    float2 ISr[8], RSr[8];
    #pragma unroll
    for (int n = 0; n < 8; ++n) {
        ISr[n] = g_IS[gc * 64 + m * 8 + n];
        RSr[n] = g_RS[gc * 64 + m * 8 + n];
    }

    const float* Yre = Y + ((size_t)(b * 16 + m)) * kFL + (size_t)f * kL;
    const float* Yim = Yre + (size_t)8 * kFL;
    float* Rre = g_rtf + ((size_t)(b * 16 + m)) * kFL + (size_t)f * kL;
    float* Rim = Rre + (size_t)8 * kFL;

    if (valid) {
        for (int t = 0; t < kLN; ++t) { Rre[t] = 0.f; Rim[t] = 0.f; }
    }

    float2 w = make_float2(0.f, 0.f);
    float  d = 1.f;

    for (int t = 0; t < kT; ++t) {
        float2 yc = make_float2(Yre[kLN + t], Yim[kLN + t]);
        float2 y = make_float2(0.f, 0.f);
        #pragma unroll
        for (int n = 0; n < 8; ++n) {
            float2 v = shfl2(yc, n);
            y.x += ISr[n].x * v.x - ISr[n].y * v.y;
            y.y += ISr[n].x * v.y + ISr[n].y * v.x;
        }
        if (t == 0) {
            float nn = y.x * y.x + y.y * y.y;
            #pragma unroll
            for (int o = 4; o; o >>= 1) nn += __shfl_xor_sync(0xffffffffu, nn, o, 8);
            float inv = 1.f / (sqrtf(nn) + 1e-8f);
            w = make_float2(y.x * inv, y.y * inv);
            d = 1.f;
        }
        float2 p = make_float2(y.x * w.x + y.y * w.y, y.y * w.x - y.x * w.y);
        #pragma unroll
        for (int o = 4; o; o >>= 1) {
            p.x += __shfl_xor_sync(0xffffffffu, p.x, o, 8);
            p.y += __shfl_xor_sync(0xffffffffu, p.y, o, 8);
        }
        d = kBETA * d + (p.x * p.x + p.y * p.y);
        float2 e = make_float2(y.x - (w.x * p.x - w.y * p.y),
                               y.y - (w.x * p.y + w.y * p.x));
        float id = 1.f / d;
        float2 cpd = make_float2(p.x * id, -p.y * id);
        w.x += e.x * cpd.x - e.y * cpd.y;
        w.y += e.x * cpd.y + e.y * cpd.x;

        float2 a = make_float2(0.f, 0.f);
        #pragma unroll
        for (int n = 0; n < 8; ++n) {
            float2 v = shfl2(w, n);
            a.x += RSr[n].x * v.x - RSr[n].y * v.y;
            a.y += RSr[n].x * v.y + RSr[n].y * v.x;
        }
        float2 rf = shfl2(a, 3);
        rf.x += 1e-6f;
        float inv2 = 1.f / (rf.x * rf.x + rf.y * rf.y);
        float ox = (a.x * rf.x + a.y * rf.y) * inv2;
        float oy = (a.y * rf.x - a.x * rf.y) * inv2;
        if (valid) { Rre[kLN + t] = ox; Rim[kLN + t] = oy; }
    }
}

// =====================================================================
// Kernel 3: Y echo + W_stage2 zeros (float4)
// =====================================================================
__global__ void k_copy(const float* __restrict__ Y, float* __restrict__ out) {
    const int NY4 = 16349312 / 4;
    const int NZ4 = 1021832 / 4;
    int i = blockIdx.x * blockDim.x + threadIdx.x;
    if (i < NY4) {
        reinterpret_cast<float4*>(out + OFF_Y)[i] = reinterpret_cast<const float4*>(Y)[i];
    } else if (i < NY4 + NZ4) {
        reinterpret_cast<float4*>(out + OFF_WS2)[i - NY4] = make_float4(0.f, 0.f, 0.f, 0.f);
    }
}

// =====================================================================
// Direct conv 3x3 (SAME): P=2 strided pixels/thread, FFMA2 accumulators,
// input double-buffer prefetch; COMPILE-TIME dims -> LDG immediate offsets
// with interior fast path (no per-tap address IMADs).
// MODE_IN : 1=concat(Y,g_rtf) 2=upsample(g_mid) 3=concat(g_u2,g_skip) 4=g_e1 5=g_d1
// MODE_OUT: 1=enc1(relu->g_e1 + fused gate) 2=out layer 10=g_d1 11=g_mid 12=g_u2
// =====================================================================
template<int CIN, int COUT, int STRIDE, int MODE_IN, int MODE_OUT, int P,
         int H_IN, int W_IN, int H_OUT, int W_OUT>
__global__ __launch_bounds__(256, 2) void k_conv(
    const float* __restrict__ Yin,
    const float* __restrict__ wgt,
    const float* __restrict__ bias,
    const float* __restrict__ gw,
    const float* __restrict__ gb,
    float* __restrict__ dout,
    int nTiles)
{
    __shared__ __align__(16) float wsh[CIN * 9 * COUT];
    __shared__ float bsh[COUT];
    __shared__ __align__(16) float gsh[(MODE_OUT == 1) ? 1024 : 4];
    __shared__ float gbsh[(MODE_OUT == 1) ? 32 : 1];

    const int b     = blockIdx.z / nTiles;
    const int ct    = blockIdx.z - b * nTiles;
    const int cbase = ct * COUT;

    for (int i = threadIdx.x; i < CIN * 9 * COUT; i += 256) {
        int ci = i / (9 * COUT);
        int r  = i - ci * 9 * COUT;
        int t  = r / COUT;
        int co = r - t * COUT;
        wsh[i] = wgt[((cbase + co) * CIN + ci) * 9 + t];
    }
    for (int i = threadIdx.x; i < COUT; i += 256) bsh[i] = bias[cbase + i];
    if (MODE_OUT == 1) {
        for (int i = threadIdx.x; i < 1024; i += 256) {
            int ci = i >> 5, co = i & 31;
            gsh[ci * 32 + co] = gw[co * 32 + ci];
        }
        if (threadIdx.x < 32) gbsh[threadIdx.x] = gb[threadIdx.x];
    }
    __syncthreads();

    const int lane = threadIdx.x & 31;
    const int f    = blockIdx.y * 8 + (threadIdx.x >> 5);
    if (f >= H_OUT) return;
    const int Lb   = blockIdx.x * (32 * P) + lane;

    // MODE_IN==2 (upsample gather) precomputed indices
    int rowbase2[3], ccol2[P][3];
    if (MODE_IN == 2) {
        #pragma unroll
        for (int kh = 0; kh < 3; ++kh) {
            int r = f + kh - 1;
            rowbase2[kh] = (r >= 0 && r < 257) ? (((2 * r + 1) * 129) / 514) * kL2 : -1;
        }
        #pragma unroll
        for (int p = 0; p < P; ++p) {
            #pragma unroll
            for (int kw = 0; kw < 3; ++kw) {
                int c = Lb + 32 * p + kw - 1;
                ccol2[p][kw] = (c >= 0 && c < 497) ? ((2 * c + 1) * 249) / 994 : -1;
            }
        }
    }

    // interior flags + center offsets (direct modes)
    bool intr[P];
    int  center[P];
    #pragma unroll
    for (int p = 0; p < P; ++p) {
        const int c0 = (Lb + 32 * p) * STRIDE;
        center[p] = f * STRIDE * W_IN + c0;
        intr[p] = (f * STRIDE >= 1) && (f * STRIDE + 1 < H_IN) &&
                  (c0 >= 1) && (c0 + 1 < W_IN);
    }

    auto srcPtr = [&](int ci) -> const float* {
        if (MODE_IN == 1)
            return (ci < 16) ? Yin + ((size_t)(b * 16 + ci)) * kFL
                             : g_rtf + ((size_t)(b * 16 + ci - 16)) * kFL;
        else if (MODE_IN == 4)
            return g_e1 + ((size_t)(b * 32 + ci)) * kFL;
        else if (MODE_IN == 5)
            return g_d1 + ((size_t)(b * 64 + ci)) * kFL2;
        else if (MODE_IN == 2)
            return g_mid + ((size_t)(b * 64 + ci)) * kFL2;
        else
            return (ci < 32) ? g_u2 + ((size_t)(b * 32 + ci)) * kFL
                             : g_skip + ((size_t)(b * 32 + ci - 32)) * kFL;
    };

    auto loadIn = [&](int ci, float* xv) {
        const float* src = srcPtr(ci);
        if (MODE_IN == 2) {
            #pragma unroll
            for (int t = 0; t < 9; ++t) {
                const int kh = t / 3, kw = t - kh * 3;
                #pragma unroll
                for (int p = 0; p < P; ++p)
                    xv[t * P + p] = (rowbase2[kh] >= 0 && ccol2[p][kw] >= 0)
                                      ? __ldg(src + rowbase2[kh] + ccol2[p][kw]) : 0.0f;
            }
        } else {
            #pragma unroll
            for (int p = 0; p < P; ++p) {
                const float* cp = src + center[p];
                if (intr[p]) {
                    // fast path: compile-time immediate offsets
                    #pragma unroll
                    for (int t = 0; t < 9; ++t) {
                        const int kh = t / 3, kw = t - kh * 3;
                        xv[t * P + p] = __ldg(cp + (kh - 1) * W_IN + (kw - 1));
                    }
                } else {
                    #pragma unroll
                    for (int t = 0; t < 9; ++t) {
                        const int kh = t / 3, kw = t - kh * 3;
                        int r = f * STRIDE + kh - 1;
                        int c = (Lb + 32 * p) * STRIDE + kw - 1;
                        xv[t * P + p] = (r >= 0 && r < H_IN && c >= 0 && c < W_IN)
                                          ? __ldg(src + r * W_IN + c) : 0.0f;
                    }
                }
            }
        }
    };

    constexpr int C2 = COUT / 2;
    unsigned long long acc2[P * C2];
    #pragma unroll
    for (int i = 0; i < C2; ++i) {
        unsigned long long bv = pack2(bsh[2 * i], bsh[2 * i + 1]);
        #pragma unroll
        for (int p = 0; p < P; ++p) acc2[p * C2 + i] = bv;
    }

    float xv[9 * P], xvn[9 * P];
    loadIn(0, xv);

    #pragma unroll 1
    for (int ci = 0; ci < CIN; ++ci) {
        if (ci + 1 < CIN) loadIn(ci + 1, xvn);   // prefetch next c_in's inputs

        const ulonglong2* wrow = reinterpret_cast<const ulonglong2*>(wsh + ci * 9 * COUT);
        #pragma unroll
        for (int t = 0; t < 9; ++t) {
            unsigned long long xx[P];
            #pragma unroll
            for (int p = 0; p < P; ++p) xx[p] = pack2(xv[t * P + p], xv[t * P + p]);
            #pragma unroll
            for (int q = 0; q < COUT / 4; ++q) {
                ulonglong2 wv = wrow[t * (COUT / 4) + q];
                #pragma unroll
                for (int p = 0; p < P; ++p) {
                    ffma2(acc2[p * C2 + 2 * q + 0], xx[p], wv.x);
                    ffma2(acc2[p * C2 + 2 * q + 1], xx[p], wv.y);
                }
            }
        }
        #pragma unroll
        for (int i = 0; i < 9 * P; ++i) xv[i] = xvn[i];
    }

    // ---------------- epilogues ----------------
    if (MODE_OUT == 1) {
        float e1v[P][32];
        #pragma unroll
        for (int p = 0; p < P; ++p) {
            #pragma unroll
            for (int i = 0; i < C2; ++i) {
                float2 v = unpack2(acc2[p * C2 + i]);
                e1v[p][2 * i]     = fmaxf(v.x, 0.0f);
                e1v[p][2 * i + 1] = fmaxf(v.y, 0.0f);
            }
        }
        #pragma unroll
        for (int p = 0; p < P; ++p) {
            const int lp = Lb + 32 * p;
            if (lp >= W_OUT) continue;
            const int pix = f * W_OUT + lp;
            float* e1dst = g_e1 + ((size_t)b * 32) * kFL + pix;
            #pragma unroll
            for (int co = 0; co < 32; ++co) e1dst[(size_t)co * kFL] = e1v[p][co];
        }

        unsigned long long ga2[P][16];
        #pragma unroll
        for (int i = 0; i < 16; ++i) {
            unsigned long long bv = pack2(gbsh[2 * i], gbsh[2 * i + 1]);
            #pragma unroll
            for (int p = 0; p < P; ++p) ga2[p][i] = bv;
        }
        #pragma unroll 1
        for (int ci = 0; ci < 32; ++ci) {
            const ulonglong2* gr = reinterpret_cast<const ulonglong2*>(gsh + ci * 32);
            unsigned long long xx[P];
            #pragma unroll
            for (int p = 0; p < P; ++p) xx[p] = pack2(e1v[p][ci], e1v[p][ci]);
            #pragma unroll
            for (int q = 0; q < 8; ++q) {
                ulonglong2 gv = gr[q];
                #pragma unroll
                for (int p = 0; p < P; ++p) {
                    ffma2(ga2[p][2 * q + 0], xx[p], gv.x);
                    ffma2(ga2[p][2 * q + 1], xx[p], gv.y);
                }
            }
        }
        #pragma unroll
        for (int p = 0; p < P; ++p) {
            const int lp = Lb + 32 * p;
            if (lp >= W_OUT) continue;
            const int pix = f * W_OUT + lp;
            float* gdst = dout + OFF_GATE + ((size_t)b * 32) * kFL + pix;
            float* sdst = g_skip + ((size_t)b * 32) * kFL + pix;
            #pragma unroll
            for (int i = 0; i < 16; ++i) {
                float2 v = unpack2(ga2[p][i]);
                float g0 = 1.0f / (1.0f + __expf(-v.x));
                float g1 = 1.0f / (1.0f + __expf(-v.y));
                gdst[(size_t)(2 * i + 0) * kFL] = g0;
                gdst[(size_t)(2 * i + 1) * kFL] = g1;
                sdst[(size_t)(2 * i + 0) * kFL] = e1v[p][2 * i + 0] * g0;
                sdst[(size_t)(2 * i + 1) * kFL] = e1v[p][2 * i + 1] * g1;
            }
        }
    } else {
        #pragma unroll
        for (int p = 0; p < P; ++p) {
            const int lp = Lb + 32 * p;
            if (lp >= W_OUT) continue;
            const int pix = f * W_OUT + lp;

            float accf[COUT];
            #pragma unroll
            for (int i = 0; i < C2; ++i) {
                float2 v = unpack2(acc2[p * C2 + i]);
                accf[2 * i] = v.x; accf[2 * i + 1] = v.y;
            }

            if (MODE_OUT == 2) {
                float wr[8], wi[8];
                #pragma unroll
                for (int co = 0; co < 16; ++co) {
                    float s = 1.0f / (1.0f + __expf(-accf[co]));
                    dout[OFF_WTC + ((size_t)(b * 16 + co)) * kFL + pix] = s;
                    if (co < 8) wr[co] = s; else wi[co - 8] = s;
                }
                float xr = 0.f;
                const float* ybase = Yin + ((size_t)b * 16) * kFL + pix;
                float* wcdst = dout + OFF_WC + ((size_t)b * 8) * kFL + pix;
                #pragma unroll
                for (int m = 0; m < 8; ++m) {
                    float yr = ybase[(size_t)m * kFL];
                    float yi = ybase[(size_t)(8 + m) * kFL];
                    xr += wr[m] * yr + wi[m] * yi;
                    wcdst[(size_t)m * kFL] = wr[m];
                }
                dout[OFF_XHAT + (size_t)b * kFL + pix] = xr;
            } else {
                float* dst;
                size_t cs;
                if (MODE_OUT == 10)      { dst = g_d1  + ((size_t)(b * 64 + cbase)) * kFL2 + pix; cs = kFL2; }
                else if (MODE_OUT == 11) { dst = g_mid + ((size_t)(b * 64 + cbase)) * kFL2 + pix; cs = kFL2; }
                else                     { dst = g_u2  + ((size_t)(b * 32 + cbase)) * kFL  + pix; cs = kFL;  }
                #pragma unroll
                for (int co = 0; co < COUT; ++co)
                    dst[(size_t)co * cs] = fmaxf(accf[co], 0.0f);
            }
        }
    }
}

// =====================================================================
extern "C" void kernel_launch(void* const* d_in, const int* in_sizes, int n_in,
                              void* d_out, int out_size)
{
    const float *Y = nullptr, *mid_w = nullptr, *gate_w = nullptr, *out_b16 = nullptr;
    const float *w9216[2]  = {nullptr, nullptr};  int n9216  = 0;
    const float *w18432[2] = {nullptr, nullptr};  int n18432 = 0;
    const float *b64[2]    = {nullptr, nullptr};  int nb64   = 0;
    const float *b32[3]    = {nullptr, nullptr, nullptr}; int nb32 = 0;
    for (int i = 0; i < n_in; ++i) {
        const float* p = (const float*)d_in[i];
        switch (in_sizes[i]) {
            case 16349312: if (!Y) Y = p; break;
            case 36864:    mid_w = p; break;
            case 1024:     gate_w = p; break;
            case 16:       out_b16 = p; break;
            case 9216:     if (n9216  < 2) w9216[n9216++]   = p; break;
            case 18432:    if (n18432 < 2) w18432[n18432++] = p; break;
            case 64:       if (nb64   < 2) b64[nb64++]      = p; break;
            case 32:       if (nb32   < 3) b32[nb32++]      = p; break;
            default: break;
        }
    }
    if (!Y || n9216 < 2 || n18432 < 2 || !mid_w || !gate_w ||
        nb64 < 2 || nb32 < 3 || !out_b16)
        return;
    if ((long long)out_size != OUT_TOTAL) return;

    const float* enc1_w = w9216[0];
    const float* out_w  = w9216[1];
    const float* down_w = w18432[0];
    const float* up_w   = w18432[1];
    const float* down_b = b64[0];
    const float* mid_b  = b64[1];
    const float* enc1_b = b32[0];
    const float* gate_b = b32[1];
    const float* up_b   = b32[2];
    float* out = (float*)d_out;

    k_prep<<<257, 256>>>(Y);
    k_scan<<<65, 256>>>(Y);
    k_copy<<<16965, 256>>>(Y, out);

    // enc1: CIN=32, COUT=32, P=2, fused gate
    k_conv<32, 32, 1, 1, 1, 2, 257, 497, 257, 497><<<dim3(8, 33, 8), 256>>>(
        Y, enc1_w, enc1_b, gate_w, gate_b, out, 1);
    // down: CIN=32, COUT=64 in 2 tiles of 32, stride 2
    k_conv<32, 32, 2, 4, 10, 2, 257, 497, 129, 249><<<dim3(4, 17, 16), 256>>>(
        Y, down_w, down_b, nullptr, nullptr, out, 2);
    // mid: CIN=64, COUT=64 in 2 tiles of 32
    k_conv<64, 32, 1, 5, 11, 2, 129, 249, 129, 249><<<dim3(4, 17, 16), 256>>>(
        Y, mid_w, mid_b, nullptr, nullptr, out, 2);
    // up: CIN=64, COUT=32 (upsample gather)
    k_conv<64, 32, 1, 2, 12, 2, 257, 497, 257, 497><<<dim3(8, 33, 8), 256>>>(
        Y, up_w, up_b, nullptr, nullptr, out, 1);
    // out: CIN=64, COUT=16, fused sigmoid/Wc/X_hat
    k_conv<64, 16, 1, 3, 2, 2, 257, 497, 257, 497><<<dim3(8, 33, 8), 256>>>(
        Y, out_w, out_b16, nullptr, nullptr, out, 1);
}